// round 8
// baseline (speedup 1.0000x reference)
#include <cuda_runtime.h>
#include <cuda_fp16.h>
#include <cstdint>

// Problem dims
#define TOKS 4096
#define HID  4096
#define INTER 14336
#define GSZ  64

// SwiGLU intermediate scaling to keep fp16 in range
#define H_SCALE   (1.0f/256.0f)
#define H_UNSCALE (256.0f)

// ---------------------------------------------------------------------------
// Device scratch
// ---------------------------------------------------------------------------
__device__ __half g_w1h[(size_t)INTER * HID];
__device__ __half g_w3h[(size_t)INTER * HID];
__device__ __half g_w2h[(size_t)HID * INTER];
__device__ __half g_xh [(size_t)TOKS * HID];
__device__ __half g_hh [(size_t)TOKS * INTER];

// ---------------------------------------------------------------------------
// PTX helpers (sm_100-base-safe: cp.async, ldmatrix, mma.sync)
// ---------------------------------------------------------------------------
static __device__ __forceinline__ uint32_t smem_u32(const void* p) {
    return (uint32_t)__cvta_generic_to_shared(p);
}
static __device__ __forceinline__ void cp16(void* s, const void* g) {
    asm volatile("cp.async.cg.shared.global [%0], [%1], 16;\n"
                 :: "r"(smem_u32(s)), "l"(g));
}
static __device__ __forceinline__ void cp_commit() {
    asm volatile("cp.async.commit_group;\n");
}
template <int N>
static __device__ __forceinline__ void cp_wait() {
    asm volatile("cp.async.wait_group %0;\n" :: "n"(N));
}
// ldmatrix on a precomputed shared-state address
static __device__ __forceinline__ void ldsm_x4u(uint32_t* r, uint32_t addr) {
    asm volatile("ldmatrix.sync.aligned.m8n8.x4.shared.b16 {%0,%1,%2,%3}, [%4];\n"
                 : "=r"(r[0]), "=r"(r[1]), "=r"(r[2]), "=r"(r[3])
                 : "r"(addr));
}
static __device__ __forceinline__ void mma_16816(float* c, const uint32_t* a,
                                                 uint32_t b0, uint32_t b1) {
    asm volatile("mma.sync.aligned.m16n8k16.row.col.f32.f16.f16.f32 "
                 "{%0,%1,%2,%3}, {%4,%5,%6,%7}, {%8,%9}, {%0,%1,%2,%3};\n"
                 : "+f"(c[0]), "+f"(c[1]), "+f"(c[2]), "+f"(c[3])
                 : "r"(a[0]), "r"(a[1]), "r"(a[2]), "r"(a[3]),
                   "r"(b0), "r"(b1));
}
static __device__ __forceinline__ float silu_f(float x) {
    return x / (1.0f + __expf(-x));
}

// ---------------------------------------------------------------------------
// Dequant: int32 codes [rows, cols] + per-group scale/zero -> fp16
// ---------------------------------------------------------------------------
__global__ void k_dequant(const int* __restrict__ q,
                          const float* __restrict__ sc,
                          const float* __restrict__ zp,
                          __half* __restrict__ out,
                          int cols, int gpc, int total8)
{
    int i = blockIdx.x * blockDim.x + threadIdx.x;
    if (i >= total8) return;
    int base = i * 8;
    int row  = base / cols;
    int col  = base - row * cols;
    int gi   = row * gpc + (col >> 6);
    float s = sc[gi];
    float z = zp[gi];
    const int4* qp = reinterpret_cast<const int4*>(q + base);
    int4 qa = qp[0];
    int4 qb = qp[1];
    __half2 p0 = __floats2half2_rn(((float)qa.x - z) * s, ((float)qa.y - z) * s);
    __half2 p1 = __floats2half2_rn(((float)qa.z - z) * s, ((float)qa.w - z) * s);
    __half2 p2 = __floats2half2_rn(((float)qb.x - z) * s, ((float)qb.y - z) * s);
    __half2 p3 = __floats2half2_rn(((float)qb.z - z) * s, ((float)qb.w - z) * s);
    uint4 o;
    o.x = *reinterpret_cast<uint32_t*>(&p0);
    o.y = *reinterpret_cast<uint32_t*>(&p1);
    o.z = *reinterpret_cast<uint32_t*>(&p2);
    o.w = *reinterpret_cast<uint32_t*>(&p3);
    *reinterpret_cast<uint4*>(out + base) = o;
}

__global__ void k_xconv(const float* __restrict__ x, int total4)
{
    int i = blockIdx.x * blockDim.x + threadIdx.x;
    if (i >= total4) return;
    float4 v = reinterpret_cast<const float4*>(x)[i];
    __half2 a = __floats2half2_rn(v.x, v.y);
    __half2 b = __floats2half2_rn(v.z, v.w);
    uint2 o;
    o.x = *reinterpret_cast<uint32_t*>(&a);
    o.y = *reinterpret_cast<uint32_t*>(&b);
    reinterpret_cast<uint2*>(g_xh)[i] = o;
}

// ---------------------------------------------------------------------------
// GEMM1 (fused gate+up): G = X*W1^T, U = X*W3^T, H = silu(G)*U*H_SCALE
// BM=128, BN=64 per matrix, BK=64, STG=3 with ONE sync per kt, 2 CTAs/SM.
// 8 warps 4(M)x2(N), warp tile 32x32 per matrix.
// ---------------------------------------------------------------------------
namespace g1 {
constexpr int BM = 128, BN = 64, BK = 64, LDK = 72, STG = 3;
constexpr int SA = BM * LDK;              // 9216 halves
constexpr int SB = BN * LDK;              // 4608 halves
constexpr int SSTAGE = SA + 2 * SB;       // 18432 halves
constexpr int STAGE_B = SSTAGE * 2;       // 36864 bytes
constexpr int SMEM_BYTES = STG * STAGE_B; // 110592
}

__global__ void __launch_bounds__(256, 2) k_gemm1()
{
    using namespace g1;
    extern __shared__ __half sm[];
    const int tid  = threadIdx.x;
    const int lane = tid & 31;
    const int warp = tid >> 5;
    const int m0 = blockIdx.x * BM;   // m fastest -> B-tile L2 reuse
    const int n0 = blockIdx.y * BN;
    const int wm = (warp & 3) * 32;
    const int wn = (warp >> 2) * 32;

    float acc1[2][4][4] = {};
    float acc3[2][4][4] = {};

    auto load_stage = [&](int s, int kt) {
        const int k0 = kt * BK;
        __half* sA  = sm + s * SSTAGE;
        __half* sB1 = sA + SA;
        __half* sB3 = sB1 + SB;
#pragma unroll
        for (int i = 0; i < 4; i++) {   // A: 1024 chunks
            int c = tid + i * 256;
            int r = c >> 3, kc = c & 7;
            cp16(sA + r * LDK + kc * 8,
                 g_xh + (size_t)(m0 + r) * HID + k0 + kc * 8);
        }
#pragma unroll
        for (int i = 0; i < 2; i++) {   // B1: 512 chunks
            int c = tid + i * 256;
            int r = c >> 3, kc = c & 7;
            cp16(sB1 + r * LDK + kc * 8,
                 g_w1h + (size_t)(n0 + r) * HID + k0 + kc * 8);
        }
#pragma unroll
        for (int i = 0; i < 2; i++) {   // B3: 512 chunks
            int c = tid + i * 256;
            int r = c >> 3, kc = c & 7;
            cp16(sB3 + r * LDK + kc * 8,
                 g_w3h + (size_t)(n0 + r) * HID + k0 + kc * 8);
        }
    };

    // Hoisted per-thread ldsm byte offsets (within a stage)
    const uint32_t smb = smem_u32(sm);
    const int a_row = lane & 15;
    const int a_col = (lane >> 4) * 8;
    const int g = lane >> 3;
    const int b_row = (g & 1) * 8 + (lane & 7);
    const int b_col = (g >> 1) * 8;
    uint32_t a_off[2], b1_off[2], b3_off[2];
#pragma unroll
    for (int mi = 0; mi < 2; mi++)
        a_off[mi] = smb + ((wm + mi * 16 + a_row) * LDK + a_col) * 2;
#pragma unroll
    for (int nj = 0; nj < 2; nj++) {
        uint32_t ro = ((wn + nj * 16 + b_row) * LDK + b_col) * 2;
        b1_off[nj] = smb + SA * 2 + ro;
        b3_off[nj] = smb + (SA + SB) * 2 + ro;
    }

    const int KT = HID / BK;  // 64
    load_stage(0, 0); cp_commit();
    load_stage(1, 1); cp_commit();

    int s_cur = 0;   // stage to compute this iteration
    int s_ld  = 2;   // stage to load this iteration (kt+2)
    for (int kt = 0; kt < KT; ++kt) {
        cp_wait<1>();            // stage kt is complete (kt+1 may be in flight)
        __syncthreads();         // all warps done reading stage (kt-1) == s_ld
        if (kt + 2 < KT) load_stage(s_ld, kt + 2);
        cp_commit();

        const uint32_t sbase = (uint32_t)s_cur * (uint32_t)STAGE_B;
#pragma unroll
        for (int kk = 0; kk < BK; kk += 16) {
            const uint32_t ko = sbase + kk * 2;
            uint32_t af[2][4];
#pragma unroll
            for (int mi = 0; mi < 2; mi++)
                ldsm_x4u(af[mi], a_off[mi] + ko);
            uint32_t b1f[2][4], b3f[2][4];
#pragma unroll
            for (int nj = 0; nj < 2; nj++) {
                ldsm_x4u(b1f[nj], b1_off[nj] + ko);
                ldsm_x4u(b3f[nj], b3_off[nj] + ko);
            }
#pragma unroll
            for (int mi = 0; mi < 2; mi++)
#pragma unroll
                for (int nj = 0; nj < 2; nj++) {
                    mma_16816(acc1[mi][2 * nj],     af[mi], b1f[nj][0], b1f[nj][2]);
                    mma_16816(acc3[mi][2 * nj],     af[mi], b3f[nj][0], b3f[nj][2]);
                    mma_16816(acc1[mi][2 * nj + 1], af[mi], b1f[nj][1], b1f[nj][3]);
                    mma_16816(acc3[mi][2 * nj + 1], af[mi], b3f[nj][1], b3f[nj][3]);
                }
        }
        s_cur = (s_cur == STG - 1) ? 0 : s_cur + 1;
        s_ld  = (s_ld  == STG - 1) ? 0 : s_ld  + 1;
    }

    // Epilogue: SwiGLU, scale, store fp16 H
#pragma unroll
    for (int mi = 0; mi < 2; mi++) {
#pragma unroll
        for (int nt = 0; nt < 4; nt++) {
            const float* a1 = acc1[mi][nt];
            const float* a3 = acc3[mi][nt];
            int row = m0 + wm + mi * 16 + (lane >> 2);
            int col = n0 + wn + nt * 8 + 2 * (lane & 3);
            float h0 = silu_f(a1[0]) * a3[0] * H_SCALE;
            float h1 = silu_f(a1[1]) * a3[1] * H_SCALE;
            float h2 = silu_f(a1[2]) * a3[2] * H_SCALE;
            float h3 = silu_f(a1[3]) * a3[3] * H_SCALE;
            __half2 lo = __floats2half2_rn(h0, h1);
            __half2 hi = __floats2half2_rn(h2, h3);
            *reinterpret_cast<__half2*>(g_hh + (size_t)row * INTER + col) = lo;
            *reinterpret_cast<__half2*>(g_hh + (size_t)(row + 8) * INTER + col) = hi;
        }
    }
}

// ---------------------------------------------------------------------------
// GEMM2 (down proj): OUT = H * W2^T * H_UNSCALE
// BM=128, BN=64, BK=64, STG=3, one sync per kt, 2 CTAs/SM.
// 8 warps 4(M)x2(N), warp 32x32. 2048 CTAs -> ~6.9 waves.
// ---------------------------------------------------------------------------
namespace g2 {
constexpr int BM = 128, BN = 64, BK = 64, LDK = 72, STG = 3;
constexpr int SA = BM * LDK;              // 9216 halves
constexpr int SB = BN * LDK;              // 4608 halves
constexpr int SSTAGE = SA + SB;           // 13824 halves
constexpr int STAGE_B = SSTAGE * 2;       // 27648 bytes
constexpr int SMEM_BYTES = STG * STAGE_B; // 82944
}

__global__ void __launch_bounds__(256, 2) k_gemm2(float* __restrict__ out)
{
    using namespace g2;
    extern __shared__ __half sm[];
    const int tid  = threadIdx.x;
    const int lane = tid & 31;
    const int warp = tid >> 5;
    const int m0 = blockIdx.x * BM;
    const int n0 = blockIdx.y * BN;
    const int wm = (warp & 3) * 32;
    const int wn = (warp >> 2) * 32;

    float acc[2][4][4] = {};

    auto load_stage = [&](int s, int kt) {
        const int k0 = kt * BK;
        __half* sA = sm + s * SSTAGE;
        __half* sB = sA + SA;
#pragma unroll
        for (int i = 0; i < 4; i++) {
            int c = tid + i * 256;
            int r = c >> 3, kc = c & 7;
            cp16(sA + r * LDK + kc * 8,
                 g_hh + (size_t)(m0 + r) * INTER + k0 + kc * 8);
        }
#pragma unroll
        for (int i = 0; i < 2; i++) {
            int c = tid + i * 256;
            int r = c >> 3, kc = c & 7;
            cp16(sB + r * LDK + kc * 8,
                 g_w2h + (size_t)(n0 + r) * INTER + k0 + kc * 8);
        }
    };

    const uint32_t smb = smem_u32(sm);
    const int a_row = lane & 15;
    const int a_col = (lane >> 4) * 8;
    const int g = lane >> 3;
    const int b_row = (g & 1) * 8 + (lane & 7);
    const int b_col = (g >> 1) * 8;
    uint32_t a_off[2], b_off[2];
#pragma unroll
    for (int mi = 0; mi < 2; mi++)
        a_off[mi] = smb + ((wm + mi * 16 + a_row) * LDK + a_col) * 2;
#pragma unroll
    for (int nj = 0; nj < 2; nj++)
        b_off[nj] = smb + SA * 2 + ((wn + nj * 16 + b_row) * LDK + b_col) * 2;

    const int KT = INTER / BK;  // 224
    load_stage(0, 0); cp_commit();
    load_stage(1, 1); cp_commit();

    int s_cur = 0;
    int s_ld  = 2;
    for (int kt = 0; kt < KT; ++kt) {
        cp_wait<1>();
        __syncthreads();
        if (kt + 2 < KT) load_stage(s_ld, kt + 2);
        cp_commit();

        const uint32_t sbase = (uint32_t)s_cur * (uint32_t)STAGE_B;
#pragma unroll
        for (int kk = 0; kk < BK; kk += 16) {
            const uint32_t ko = sbase + kk * 2;
            uint32_t af[2][4];
#pragma unroll
            for (int mi = 0; mi < 2; mi++)
                ldsm_x4u(af[mi], a_off[mi] + ko);
            uint32_t bf[2][4];
#pragma unroll
            for (int nj = 0; nj < 2; nj++)
                ldsm_x4u(bf[nj], b_off[nj] + ko);
#pragma unroll
            for (int mi = 0; mi < 2; mi++)
#pragma unroll
                for (int nj = 0; nj < 2; nj++) {
                    mma_16816(acc[mi][2 * nj],     af[mi], bf[nj][0], bf[nj][2]);
                    mma_16816(acc[mi][2 * nj + 1], af[mi], bf[nj][1], bf[nj][3]);
                }
        }
        s_cur = (s_cur == STG - 1) ? 0 : s_cur + 1;
        s_ld  = (s_ld  == STG - 1) ? 0 : s_ld  + 1;
    }

#pragma unroll
    for (int mi = 0; mi < 2; mi++) {
#pragma unroll
        for (int nt = 0; nt < 4; nt++) {
            const float* a = acc[mi][nt];
            int row = m0 + wm + mi * 16 + (lane >> 2);
            int col = n0 + wn + nt * 8 + 2 * (lane & 3);
            float2 lo = make_float2(a[0] * H_UNSCALE, a[1] * H_UNSCALE);
            float2 hi = make_float2(a[2] * H_UNSCALE, a[3] * H_UNSCALE);
            *reinterpret_cast<float2*>(out + (size_t)row * HID + col) = lo;
            *reinterpret_cast<float2*>(out + (size_t)(row + 8) * HID + col) = hi;
        }
    }
}

// ---------------------------------------------------------------------------
// Launch. k_gemm1 stays at launch index 4 (the slot ncu samples).
// ---------------------------------------------------------------------------
extern "C" void kernel_launch(void* const* d_in, const int* in_sizes, int n_in,
                              void* d_out, int out_size)
{
    (void)in_sizes; (void)n_in; (void)out_size;
    const float* x   = (const float*)d_in[0];
    const int*   w1q = (const int*)  d_in[1];
    const float* w1s = (const float*)d_in[2];
    const float* w1z = (const float*)d_in[3];
    const int*   w3q = (const int*)  d_in[4];
    const float* w3s = (const float*)d_in[5];
    const float* w3z = (const float*)d_in[6];
    const int*   w2q = (const int*)  d_in[7];
    const float* w2s = (const float*)d_in[8];
    const float* w2z = (const float*)d_in[9];
    float* out = (float*)d_out;

    void* p;
    cudaGetSymbolAddress(&p, g_w1h); __half* w1h = (__half*)p;
    cudaGetSymbolAddress(&p, g_w3h); __half* w3h = (__half*)p;
    cudaGetSymbolAddress(&p, g_w2h); __half* w2h = (__half*)p;

    cudaFuncSetAttribute(k_gemm1, cudaFuncAttributeMaxDynamicSharedMemorySize,
                         g1::SMEM_BYTES);
    cudaFuncSetAttribute(k_gemm2, cudaFuncAttributeMaxDynamicSharedMemorySize,
                         g2::SMEM_BYTES);

    int t8 = INTER * HID / 8;
    int blocks = (t8 + 255) / 256;
    int t4 = TOKS * HID / 4;

    // 1, 2, 3: inputs of GEMM1
    k_dequant<<<blocks, 256>>>(w1q, w1s, w1z, w1h, HID, HID / GSZ, t8);
    k_dequant<<<blocks, 256>>>(w3q, w3s, w3z, w3h, HID, HID / GSZ, t8);
    k_xconv<<<(t4 + 255) / 256, 256>>>(x, t4);
    // 4: GEMM1 (gate/up + SwiGLU)
    k_gemm1<<<dim3(TOKS / g1::BM, INTER / g1::BN), 256, g1::SMEM_BYTES>>>();
    // 5: dequant W2 (only needed by GEMM2)
    k_dequant<<<blocks, 256>>>(w2q, w2s, w2z, w2h, INTER, INTER / GSZ, t8);
    // 6: GEMM2 (down proj)
    k_gemm2<<<dim3(TOKS / g2::BM, HID / g2::BN), 256, g2::SMEM_BYTES>>>(out);
}

// round 9
// speedup vs baseline: 1.0263x; 1.0263x over previous
#include <cuda_runtime.h>
#include <cuda_fp16.h>
#include <cstdint>

// Problem dims
#define TOKS 4096
#define HID  4096
#define INTER 14336
#define GSZ  64

// SwiGLU intermediate scaling to keep fp16 in range
#define H_SCALE   (1.0f/256.0f)
#define H_UNSCALE (256.0f)

// ---------------------------------------------------------------------------
// Device scratch
// ---------------------------------------------------------------------------
__device__ __half g_w1h[(size_t)INTER * HID];
__device__ __half g_w3h[(size_t)INTER * HID];
__device__ __half g_w2h[(size_t)HID * INTER];
__device__ __half g_xh [(size_t)TOKS * HID];
__device__ __half g_hh [(size_t)TOKS * INTER];

// ---------------------------------------------------------------------------
// PTX helpers (sm_100-base-safe: cp.async, ldmatrix, mma.sync)
// ---------------------------------------------------------------------------
static __device__ __forceinline__ uint32_t smem_u32(const void* p) {
    return (uint32_t)__cvta_generic_to_shared(p);
}
static __device__ __forceinline__ void cp16(void* s, const void* g) {
    asm volatile("cp.async.cg.shared.global [%0], [%1], 16;\n"
                 :: "r"(smem_u32(s)), "l"(g));
}
static __device__ __forceinline__ void cp_commit() {
    asm volatile("cp.async.commit_group;\n");
}
template <int N>
static __device__ __forceinline__ void cp_wait() {
    asm volatile("cp.async.wait_group %0;\n" :: "n"(N));
}
static __device__ __forceinline__ void ldsm_x4u(uint32_t* r, uint32_t addr) {
    asm volatile("ldmatrix.sync.aligned.m8n8.x4.shared.b16 {%0,%1,%2,%3}, [%4];\n"
                 : "=r"(r[0]), "=r"(r[1]), "=r"(r[2]), "=r"(r[3])
                 : "r"(addr));
}
static __device__ __forceinline__ void mma_16816(float* c, const uint32_t* a,
                                                 uint32_t b0, uint32_t b1) {
    asm volatile("mma.sync.aligned.m16n8k16.row.col.f32.f16.f16.f32 "
                 "{%0,%1,%2,%3}, {%4,%5,%6,%7}, {%8,%9}, {%0,%1,%2,%3};\n"
                 : "+f"(c[0]), "+f"(c[1]), "+f"(c[2]), "+f"(c[3])
                 : "r"(a[0]), "r"(a[1]), "r"(a[2]), "r"(a[3]),
                   "r"(b0), "r"(b1));
}
static __device__ __forceinline__ float silu_f(float x) {
    return x / (1.0f + __expf(-x));
}

// ---------------------------------------------------------------------------
// Dequant: int32 codes [rows, cols] + per-group scale/zero -> fp16
// ---------------------------------------------------------------------------
__global__ void k_dequant(const int* __restrict__ q,
                          const float* __restrict__ sc,
                          const float* __restrict__ zp,
                          __half* __restrict__ out,
                          int cols, int gpc, int total8)
{
    int i = blockIdx.x * blockDim.x + threadIdx.x;
    if (i >= total8) return;
    int base = i * 8;
    int row  = base / cols;
    int col  = base - row * cols;
    int gi   = row * gpc + (col >> 6);
    float s = sc[gi];
    float z = zp[gi];
    const int4* qp = reinterpret_cast<const int4*>(q + base);
    int4 qa = qp[0];
    int4 qb = qp[1];
    __half2 p0 = __floats2half2_rn(((float)qa.x - z) * s, ((float)qa.y - z) * s);
    __half2 p1 = __floats2half2_rn(((float)qa.z - z) * s, ((float)qa.w - z) * s);
    __half2 p2 = __floats2half2_rn(((float)qb.x - z) * s, ((float)qb.y - z) * s);
    __half2 p3 = __floats2half2_rn(((float)qb.z - z) * s, ((float)qb.w - z) * s);
    uint4 o;
    o.x = *reinterpret_cast<uint32_t*>(&p0);
    o.y = *reinterpret_cast<uint32_t*>(&p1);
    o.z = *reinterpret_cast<uint32_t*>(&p2);
    o.w = *reinterpret_cast<uint32_t*>(&p3);
    *reinterpret_cast<uint4*>(out + base) = o;
}

__global__ void k_xconv(const float* __restrict__ x, int total4)
{
    int i = blockIdx.x * blockDim.x + threadIdx.x;
    if (i >= total4) return;
    float4 v = reinterpret_cast<const float4*>(x)[i];
    __half2 a = __floats2half2_rn(v.x, v.y);
    __half2 b = __floats2half2_rn(v.z, v.w);
    uint2 o;
    o.x = *reinterpret_cast<uint32_t*>(&a);
    o.y = *reinterpret_cast<uint32_t*>(&b);
    reinterpret_cast<uint2*>(g_xh)[i] = o;
}

// ---------------------------------------------------------------------------
// GEMM1 (fused gate+up): G = X*W1^T, U = X*W3^T, H = silu(G)*U*H_SCALE
// BM=64, BN=64 per matrix, BK=64, STG=2, 128 threads, 3 CTAs/SM.
// 4 warps 2(M)x2(N), warp tile 32x32 per matrix.
// Fragment double-buffering: ldsm for kk+1 issued before mma of kk.
// ---------------------------------------------------------------------------
namespace g1 {
constexpr int BM = 64, BN = 64, BK = 64, LDK = 72, STG = 2;
constexpr int SA = BM * LDK;              // 4608 halves
constexpr int SB = BN * LDK;              // 4608 halves
constexpr int SSTAGE = SA + 2 * SB;       // 13824 halves
constexpr int STAGE_B = SSTAGE * 2;       // 27648 bytes
constexpr int SMEM_BYTES = STG * STAGE_B; // 55296
}

__global__ void __launch_bounds__(128, 3) k_gemm1()
{
    using namespace g1;
    extern __shared__ __half sm[];
    const int tid  = threadIdx.x;
    const int lane = tid & 31;
    const int warp = tid >> 5;
    const int m0 = blockIdx.x * BM;   // m fastest -> B-tile L2 reuse
    const int n0 = blockIdx.y * BN;
    const int wm = (warp & 1) * 32;
    const int wn = (warp >> 1) * 32;

    float acc1[2][4][4] = {};
    float acc3[2][4][4] = {};

    auto load_stage = [&](int s, int kt) {
        const int k0 = kt * BK;
        __half* sA  = sm + s * SSTAGE;
        __half* sB1 = sA + SA;
        __half* sB3 = sB1 + SB;
#pragma unroll
        for (int i = 0; i < 4; i++) {   // A: 512 chunks
            int c = tid + i * 128;
            int r = c >> 3, kc = c & 7;
            cp16(sA + r * LDK + kc * 8,
                 g_xh + (size_t)(m0 + r) * HID + k0 + kc * 8);
        }
#pragma unroll
        for (int i = 0; i < 4; i++) {   // B1: 512 chunks
            int c = tid + i * 128;
            int r = c >> 3, kc = c & 7;
            cp16(sB1 + r * LDK + kc * 8,
                 g_w1h + (size_t)(n0 + r) * HID + k0 + kc * 8);
        }
#pragma unroll
        for (int i = 0; i < 4; i++) {   // B3: 512 chunks
            int c = tid + i * 128;
            int r = c >> 3, kc = c & 7;
            cp16(sB3 + r * LDK + kc * 8,
                 g_w3h + (size_t)(n0 + r) * HID + k0 + kc * 8);
        }
    };

    // Hoisted per-thread ldsm byte offsets (within a stage)
    const uint32_t smb = smem_u32(sm);
    const int a_row = lane & 15;
    const int a_col = (lane >> 4) * 8;
    const int g = lane >> 3;
    const int b_row = (g & 1) * 8 + (lane & 7);
    const int b_col = (g >> 1) * 8;
    uint32_t a_off[2], b1_off[2], b3_off[2];
#pragma unroll
    for (int mi = 0; mi < 2; mi++)
        a_off[mi] = smb + ((wm + mi * 16 + a_row) * LDK + a_col) * 2;
#pragma unroll
    for (int nj = 0; nj < 2; nj++) {
        uint32_t ro = ((wn + nj * 16 + b_row) * LDK + b_col) * 2;
        b1_off[nj] = smb + SA * 2 + ro;
        b3_off[nj] = smb + (SA + SB) * 2 + ro;
    }

    const int KT = HID / BK;  // 64
    load_stage(0, 0);
    cp_commit();

    // Double-buffered fragments
    uint32_t af[2][2][4], b1f[2][2][4], b3f[2][2][4];

    for (int kt = 0; kt < KT; ++kt) {
        cp_wait<0>();
        __syncthreads();
        if (kt + 1 < KT) load_stage((kt + 1) & 1, kt + 1);
        cp_commit();

        const uint32_t sbase = (kt & 1) * (uint32_t)STAGE_B;
        // Preload kk=0 fragments into buffer 0
#pragma unroll
        for (int mi = 0; mi < 2; mi++) ldsm_x4u(af[0][mi], a_off[mi] + sbase);
#pragma unroll
        for (int nj = 0; nj < 2; nj++) {
            ldsm_x4u(b1f[0][nj], b1_off[nj] + sbase);
            ldsm_x4u(b3f[0][nj], b3_off[nj] + sbase);
        }
#pragma unroll
        for (int kk16 = 0; kk16 < 4; kk16++) {
            const int cur = kk16 & 1;
            const int nxt = cur ^ 1;
            if (kk16 < 3) {   // prefetch next kk fragments before mma
                const uint32_t ko = sbase + (uint32_t)(kk16 + 1) * 32;
#pragma unroll
                for (int mi = 0; mi < 2; mi++) ldsm_x4u(af[nxt][mi], a_off[mi] + ko);
#pragma unroll
                for (int nj = 0; nj < 2; nj++) {
                    ldsm_x4u(b1f[nxt][nj], b1_off[nj] + ko);
                    ldsm_x4u(b3f[nxt][nj], b3_off[nj] + ko);
                }
            }
#pragma unroll
            for (int mi = 0; mi < 2; mi++)
#pragma unroll
                for (int nj = 0; nj < 2; nj++) {
                    mma_16816(acc1[mi][2 * nj],     af[cur][mi], b1f[cur][nj][0], b1f[cur][nj][2]);
                    mma_16816(acc3[mi][2 * nj],     af[cur][mi], b3f[cur][nj][0], b3f[cur][nj][2]);
                    mma_16816(acc1[mi][2 * nj + 1], af[cur][mi], b1f[cur][nj][1], b1f[cur][nj][3]);
                    mma_16816(acc3[mi][2 * nj + 1], af[cur][mi], b3f[cur][nj][1], b3f[cur][nj][3]);
                }
        }
    }

    // Epilogue: SwiGLU, scale, store fp16 H
#pragma unroll
    for (int mi = 0; mi < 2; mi++) {
#pragma unroll
        for (int nt = 0; nt < 4; nt++) {
            const float* a1 = acc1[mi][nt];
            const float* a3 = acc3[mi][nt];
            int row = m0 + wm + mi * 16 + (lane >> 2);
            int col = n0 + wn + nt * 8 + 2 * (lane & 3);
            float h0 = silu_f(a1[0]) * a3[0] * H_SCALE;
            float h1 = silu_f(a1[1]) * a3[1] * H_SCALE;
            float h2 = silu_f(a1[2]) * a3[2] * H_SCALE;
            float h3 = silu_f(a1[3]) * a3[3] * H_SCALE;
            __half2 lo = __floats2half2_rn(h0, h1);
            __half2 hi = __floats2half2_rn(h2, h3);
            *reinterpret_cast<__half2*>(g_hh + (size_t)row * INTER + col) = lo;
            *reinterpret_cast<__half2*>(g_hh + (size_t)(row + 8) * INTER + col) = hi;
        }
    }
}

// ---------------------------------------------------------------------------
// GEMM2 (down proj): OUT = H * W2^T * H_UNSCALE
// BM=64, BN=64, BK=64, STG=2, 128 threads, 3 CTAs/SM.
// 4 warps 2(M)x2(N), warp tile 32x32, double-buffered fragments.
// ---------------------------------------------------------------------------
namespace g2 {
constexpr int BM = 64, BN = 64, BK = 64, LDK = 72, STG = 2;
constexpr int SA = BM * LDK;              // 4608 halves
constexpr int SB = BN * LDK;              // 4608 halves
constexpr int SSTAGE = SA + SB;           // 9216 halves
constexpr int STAGE_B = SSTAGE * 2;       // 18432 bytes
constexpr int SMEM_BYTES = STG * STAGE_B; // 36864
}

__global__ void __launch_bounds__(128, 3) k_gemm2(float* __restrict__ out)
{
    using namespace g2;
    extern __shared__ __half sm[];
    const int tid  = threadIdx.x;
    const int lane = tid & 31;
    const int warp = tid >> 5;
    const int m0 = blockIdx.x * BM;
    const int n0 = blockIdx.y * BN;
    const int wm = (warp & 1) * 32;
    const int wn = (warp >> 1) * 32;

    float acc[2][4][4] = {};

    auto load_stage = [&](int s, int kt) {
        const int k0 = kt * BK;
        __half* sA = sm + s * SSTAGE;
        __half* sB = sA + SA;
#pragma unroll
        for (int i = 0; i < 4; i++) {
            int c = tid + i * 128;
            int r = c >> 3, kc = c & 7;
            cp16(sA + r * LDK + kc * 8,
                 g_hh + (size_t)(m0 + r) * INTER + k0 + kc * 8);
        }
#pragma unroll
        for (int i = 0; i < 4; i++) {
            int c = tid + i * 128;
            int r = c >> 3, kc = c & 7;
            cp16(sB + r * LDK + kc * 8,
                 g_w2h + (size_t)(n0 + r) * INTER + k0 + kc * 8);
        }
    };

    const uint32_t smb = smem_u32(sm);
    const int a_row = lane & 15;
    const int a_col = (lane >> 4) * 8;
    const int g = lane >> 3;
    const int b_row = (g & 1) * 8 + (lane & 7);
    const int b_col = (g >> 1) * 8;
    uint32_t a_off[2], b_off[2];
#pragma unroll
    for (int mi = 0; mi < 2; mi++)
        a_off[mi] = smb + ((wm + mi * 16 + a_row) * LDK + a_col) * 2;
#pragma unroll
    for (int nj = 0; nj < 2; nj++)
        b_off[nj] = smb + SA * 2 + ((wn + nj * 16 + b_row) * LDK + b_col) * 2;

    const int KT = INTER / BK;  // 224
    load_stage(0, 0);
    cp_commit();

    uint32_t af[2][2][4], bf[2][2][4];

    for (int kt = 0; kt < KT; ++kt) {
        cp_wait<0>();
        __syncthreads();
        if (kt + 1 < KT) load_stage((kt + 1) & 1, kt + 1);
        cp_commit();

        const uint32_t sbase = (kt & 1) * (uint32_t)STAGE_B;
#pragma unroll
        for (int mi = 0; mi < 2; mi++) ldsm_x4u(af[0][mi], a_off[mi] + sbase);
#pragma unroll
        for (int nj = 0; nj < 2; nj++) ldsm_x4u(bf[0][nj], b_off[nj] + sbase);
#pragma unroll
        for (int kk16 = 0; kk16 < 4; kk16++) {
            const int cur = kk16 & 1;
            const int nxt = cur ^ 1;
            if (kk16 < 3) {
                const uint32_t ko = sbase + (uint32_t)(kk16 + 1) * 32;
#pragma unroll
                for (int mi = 0; mi < 2; mi++) ldsm_x4u(af[nxt][mi], a_off[mi] + ko);
#pragma unroll
                for (int nj = 0; nj < 2; nj++) ldsm_x4u(bf[nxt][nj], b_off[nj] + ko);
            }
#pragma unroll
            for (int mi = 0; mi < 2; mi++)
#pragma unroll
                for (int nj = 0; nj < 2; nj++) {
                    mma_16816(acc[mi][2 * nj],     af[cur][mi], bf[cur][nj][0], bf[cur][nj][2]);
                    mma_16816(acc[mi][2 * nj + 1], af[cur][mi], bf[cur][nj][1], bf[cur][nj][3]);
                }
        }
    }

#pragma unroll
    for (int mi = 0; mi < 2; mi++) {
#pragma unroll
        for (int nt = 0; nt < 4; nt++) {
            const float* a = acc[mi][nt];
            int row = m0 + wm + mi * 16 + (lane >> 2);
            int col = n0 + wn + nt * 8 + 2 * (lane & 3);
            float2 lo = make_float2(a[0] * H_UNSCALE, a[1] * H_UNSCALE);
            float2 hi = make_float2(a[2] * H_UNSCALE, a[3] * H_UNSCALE);
            *reinterpret_cast<float2*>(out + (size_t)row * HID + col) = lo;
            *reinterpret_cast<float2*>(out + (size_t)(row + 8) * HID + col) = hi;
        }
    }
}

// ---------------------------------------------------------------------------
// Launch. k_gemm1 stays at launch index 4 (the slot ncu samples).
// ---------------------------------------------------------------------------
extern "C" void kernel_launch(void* const* d_in, const int* in_sizes, int n_in,
                              void* d_out, int out_size)
{
    (void)in_sizes; (void)n_in; (void)out_size;
    const float* x   = (const float*)d_in[0];
    const int*   w1q = (const int*)  d_in[1];
    const float* w1s = (const float*)d_in[2];
    const float* w1z = (const float*)d_in[3];
    const int*   w3q = (const int*)  d_in[4];
    const float* w3s = (const float*)d_in[5];
    const float* w3z = (const float*)d_in[6];
    const int*   w2q = (const int*)  d_in[7];
    const float* w2s = (const float*)d_in[8];
    const float* w2z = (const float*)d_in[9];
    float* out = (float*)d_out;

    void* p;
    cudaGetSymbolAddress(&p, g_w1h); __half* w1h = (__half*)p;
    cudaGetSymbolAddress(&p, g_w3h); __half* w3h = (__half*)p;
    cudaGetSymbolAddress(&p, g_w2h); __half* w2h = (__half*)p;

    cudaFuncSetAttribute(k_gemm1, cudaFuncAttributeMaxDynamicSharedMemorySize,
                         g1::SMEM_BYTES);
    cudaFuncSetAttribute(k_gemm2, cudaFuncAttributeMaxDynamicSharedMemorySize,
                         g2::SMEM_BYTES);

    int t8 = INTER * HID / 8;
    int blocks = (t8 + 255) / 256;
    int t4 = TOKS * HID / 4;

    // 1, 2, 3: inputs of GEMM1
    k_dequant<<<blocks, 256>>>(w1q, w1s, w1z, w1h, HID, HID / GSZ, t8);
    k_dequant<<<blocks, 256>>>(w3q, w3s, w3z, w3h, HID, HID / GSZ, t8);
    k_xconv<<<(t4 + 255) / 256, 256>>>(x, t4);
    // 4: GEMM1 (gate/up + SwiGLU)
    k_gemm1<<<dim3(TOKS / g1::BM, INTER / g1::BN), 128, g1::SMEM_BYTES>>>();
    // 5: dequant W2 (only needed by GEMM2)
    k_dequant<<<blocks, 256>>>(w2q, w2s, w2z, w2h, INTER, INTER / GSZ, t8);
    // 6: GEMM2 (down proj)
    k_gemm2<<<dim3(TOKS / g2::BM, HID / g2::BN), 128, g2::SMEM_BYTES>>>(out);
}

// round 10
// speedup vs baseline: 1.0372x; 1.0106x over previous
#include <cuda_runtime.h>
#include <cuda_fp16.h>
#include <cstdint>

// Problem dims
#define TOKS 4096
#define HID  4096
#define INTER 14336
#define GSZ  64

// SwiGLU intermediate scaling to keep fp16 in range
#define H_SCALE   (1.0f/256.0f)
#define H_UNSCALE (256.0f)

// ---------------------------------------------------------------------------
// Device scratch
// ---------------------------------------------------------------------------
__device__ __half g_w1h[(size_t)INTER * HID];
__device__ __half g_w3h[(size_t)INTER * HID];
__device__ __half g_w2h[(size_t)HID * INTER];
__device__ __half g_xh [(size_t)TOKS * HID];
__device__ __half g_hh [(size_t)TOKS * INTER];

// ---------------------------------------------------------------------------
// PTX helpers (sm_100-base-safe: cp.async, ldmatrix, mma.sync)
// ---------------------------------------------------------------------------
static __device__ __forceinline__ uint32_t smem_u32(const void* p) {
    return (uint32_t)__cvta_generic_to_shared(p);
}
static __device__ __forceinline__ void cp16(void* s, const void* g) {
    asm volatile("cp.async.cg.shared.global [%0], [%1], 16;\n"
                 :: "r"(smem_u32(s)), "l"(g));
}
static __device__ __forceinline__ void cp_commit() {
    asm volatile("cp.async.commit_group;\n");
}
template <int N>
static __device__ __forceinline__ void cp_wait() {
    asm volatile("cp.async.wait_group %0;\n" :: "n"(N));
}
static __device__ __forceinline__ void ldsm_x4u(uint32_t* r, uint32_t addr) {
    asm volatile("ldmatrix.sync.aligned.m8n8.x4.shared.b16 {%0,%1,%2,%3}, [%4];\n"
                 : "=r"(r[0]), "=r"(r[1]), "=r"(r[2]), "=r"(r[3])
                 : "r"(addr));
}
static __device__ __forceinline__ void mma_16816(float* c, const uint32_t* a,
                                                 uint32_t b0, uint32_t b1) {
    asm volatile("mma.sync.aligned.m16n8k16.row.col.f32.f16.f16.f32 "
                 "{%0,%1,%2,%3}, {%4,%5,%6,%7}, {%8,%9}, {%0,%1,%2,%3};\n"
                 : "+f"(c[0]), "+f"(c[1]), "+f"(c[2]), "+f"(c[3])
                 : "r"(a[0]), "r"(a[1]), "r"(a[2]), "r"(a[3]),
                   "r"(b0), "r"(b1));
}
static __device__ __forceinline__ float silu_f(float x) {
    return x / (1.0f + __expf(-x));
}

// ---------------------------------------------------------------------------
// Dequant: int32 codes [rows, cols] + per-group scale/zero -> fp16
// ---------------------------------------------------------------------------
__global__ void k_dequant(const int* __restrict__ q,
                          const float* __restrict__ sc,
                          const float* __restrict__ zp,
                          __half* __restrict__ out,
                          int cols, int gpc, int total8)
{
    int i = blockIdx.x * blockDim.x + threadIdx.x;
    if (i >= total8) return;
    int base = i * 8;
    int row  = base / cols;
    int col  = base - row * cols;
    int gi   = row * gpc + (col >> 6);
    float s = sc[gi];
    float z = zp[gi];
    const int4* qp = reinterpret_cast<const int4*>(q + base);
    int4 qa = qp[0];
    int4 qb = qp[1];
    __half2 p0 = __floats2half2_rn(((float)qa.x - z) * s, ((float)qa.y - z) * s);
    __half2 p1 = __floats2half2_rn(((float)qa.z - z) * s, ((float)qa.w - z) * s);
    __half2 p2 = __floats2half2_rn(((float)qb.x - z) * s, ((float)qb.y - z) * s);
    __half2 p3 = __floats2half2_rn(((float)qb.z - z) * s, ((float)qb.w - z) * s);
    uint4 o;
    o.x = *reinterpret_cast<uint32_t*>(&p0);
    o.y = *reinterpret_cast<uint32_t*>(&p1);
    o.z = *reinterpret_cast<uint32_t*>(&p2);
    o.w = *reinterpret_cast<uint32_t*>(&p3);
    *reinterpret_cast<uint4*>(out + base) = o;
}

__global__ void k_xconv(const float* __restrict__ x, int total4)
{
    int i = blockIdx.x * blockDim.x + threadIdx.x;
    if (i >= total4) return;
    float4 v = reinterpret_cast<const float4*>(x)[i];
    __half2 a = __floats2half2_rn(v.x, v.y);
    __half2 b = __floats2half2_rn(v.z, v.w);
    uint2 o;
    o.x = *reinterpret_cast<uint32_t*>(&a);
    o.y = *reinterpret_cast<uint32_t*>(&b);
    reinterpret_cast<uint2*>(g_xh)[i] = o;
}

// ---------------------------------------------------------------------------
// GEMM1 (fused gate+up): G = X*W1^T, U = X*W3^T, H = silu(G)*U*H_SCALE
// CTA: 128 threads, tile M128 x N64 per matrix, BK=64, STG=2, 2 CTAs/SM.
// 4 warps 2(M)x2(N); warp tile M64 x N32 per matrix.
// smem/mma: LDS 125 B + STS 72 B (vs 272 in round 9).
// ---------------------------------------------------------------------------
namespace g1 {
constexpr int BM = 128, BN = 64, BK = 64, LDK = 72, STG = 2;
constexpr int SA = BM * LDK;              // 9216 halves
constexpr int SB = BN * LDK;              // 4608 halves
constexpr int SSTAGE = SA + 2 * SB;       // 18432 halves
constexpr int STAGE_B = SSTAGE * 2;       // 36864 bytes
constexpr int SMEM_BYTES = STG * STAGE_B; // 73728
}

__global__ void __launch_bounds__(128, 2) k_gemm1()
{
    using namespace g1;
    extern __shared__ __half sm[];
    const int tid  = threadIdx.x;
    const int lane = tid & 31;
    const int warp = tid >> 5;
    const int m0 = blockIdx.x * BM;   // m fastest -> B-tile L2 reuse
    const int n0 = blockIdx.y * BN;
    const int wm = (warp & 1) * 64;   // warp M offset (64 rows)
    const int wn = (warp >> 1) * 32;  // warp N offset (32 cols per matrix)

    float acc1[4][4][4] = {};   // [mi][nt][4], mi: 4 x m16, nt: 4 x n8
    float acc3[4][4][4] = {};

    auto load_stage = [&](int s, int kt) {
        const int k0 = kt * BK;
        __half* sA  = sm + s * SSTAGE;
        __half* sB1 = sA + SA;
        __half* sB3 = sB1 + SB;
#pragma unroll
        for (int i = 0; i < 8; i++) {   // A: 1024 chunks of 16B
            int c = tid + i * 128;
            int r = c >> 3, kc = c & 7;
            cp16(sA + r * LDK + kc * 8,
                 g_xh + (size_t)(m0 + r) * HID + k0 + kc * 8);
        }
#pragma unroll
        for (int i = 0; i < 4; i++) {   // B1: 512 chunks
            int c = tid + i * 128;
            int r = c >> 3, kc = c & 7;
            cp16(sB1 + r * LDK + kc * 8,
                 g_w1h + (size_t)(n0 + r) * HID + k0 + kc * 8);
        }
#pragma unroll
        for (int i = 0; i < 4; i++) {   // B3: 512 chunks
            int c = tid + i * 128;
            int r = c >> 3, kc = c & 7;
            cp16(sB3 + r * LDK + kc * 8,
                 g_w3h + (size_t)(n0 + r) * HID + k0 + kc * 8);
        }
    };

    // Hoisted per-thread ldsm byte offsets (within a stage)
    const uint32_t smb = smem_u32(sm);
    const int a_row = lane & 15;
    const int a_col = (lane >> 4) * 8;
    const int g = lane >> 3;
    const int b_row = (g & 1) * 8 + (lane & 7);
    const int b_col = (g >> 1) * 8;
    uint32_t a_off[4], b1_off[2], b3_off[2];
#pragma unroll
    for (int mi = 0; mi < 4; mi++)
        a_off[mi] = smb + ((wm + mi * 16 + a_row) * LDK + a_col) * 2;
#pragma unroll
    for (int nj = 0; nj < 2; nj++) {
        uint32_t ro = ((wn + nj * 16 + b_row) * LDK + b_col) * 2;
        b1_off[nj] = smb + SA * 2 + ro;
        b3_off[nj] = smb + (SA + SB) * 2 + ro;
    }

    const int KT = HID / BK;  // 64
    load_stage(0, 0);
    cp_commit();

    for (int kt = 0; kt < KT; ++kt) {
        cp_wait<0>();
        __syncthreads();
        if (kt + 1 < KT) load_stage((kt + 1) & 1, kt + 1);
        cp_commit();

        const uint32_t sbase = (kt & 1) * (uint32_t)STAGE_B;
#pragma unroll
        for (int kk16 = 0; kk16 < 4; kk16++) {
            const uint32_t ko = sbase + (uint32_t)kk16 * 32;
            uint32_t af[4][4];
#pragma unroll
            for (int mi = 0; mi < 4; mi++)
                ldsm_x4u(af[mi], a_off[mi] + ko);
            uint32_t b1f[2][4], b3f[2][4];
#pragma unroll
            for (int nj = 0; nj < 2; nj++) {
                ldsm_x4u(b1f[nj], b1_off[nj] + ko);
                ldsm_x4u(b3f[nj], b3_off[nj] + ko);
            }
#pragma unroll
            for (int mi = 0; mi < 4; mi++)
#pragma unroll
                for (int nj = 0; nj < 2; nj++) {
                    mma_16816(acc1[mi][2 * nj],     af[mi], b1f[nj][0], b1f[nj][2]);
                    mma_16816(acc3[mi][2 * nj],     af[mi], b3f[nj][0], b3f[nj][2]);
                    mma_16816(acc1[mi][2 * nj + 1], af[mi], b1f[nj][1], b1f[nj][3]);
                    mma_16816(acc3[mi][2 * nj + 1], af[mi], b3f[nj][1], b3f[nj][3]);
                }
        }
    }

    // Epilogue: SwiGLU, scale, store fp16 H
#pragma unroll
    for (int mi = 0; mi < 4; mi++) {
#pragma unroll
        for (int nt = 0; nt < 4; nt++) {
            const float* a1 = acc1[mi][nt];
            const float* a3 = acc3[mi][nt];
            int row = m0 + wm + mi * 16 + (lane >> 2);
            int col = n0 + wn + nt * 8 + 2 * (lane & 3);
            float h0 = silu_f(a1[0]) * a3[0] * H_SCALE;
            float h1 = silu_f(a1[1]) * a3[1] * H_SCALE;
            float h2 = silu_f(a1[2]) * a3[2] * H_SCALE;
            float h3 = silu_f(a1[3]) * a3[3] * H_SCALE;
            __half2 lo = __floats2half2_rn(h0, h1);
            __half2 hi = __floats2half2_rn(h2, h3);
            *reinterpret_cast<__half2*>(g_hh + (size_t)row * INTER + col) = lo;
            *reinterpret_cast<__half2*>(g_hh + (size_t)(row + 8) * INTER + col) = hi;
        }
    }
}

// ---------------------------------------------------------------------------
// GEMM2 (down proj): OUT = H * W2^T * H_UNSCALE
// CTA: 128 threads, tile M128 x N128, BK=64, STG=2, 2 CTAs/SM.
// 4 warps 2(M)x2(N); warp tile 64x64.
// smem/mma: LDS 125 B + STS 72 B.
// ---------------------------------------------------------------------------
namespace g2 {
constexpr int BM = 128, BN = 128, BK = 64, LDK = 72, STG = 2;
constexpr int SA = BM * LDK;              // 9216 halves
constexpr int SB = BN * LDK;              // 9216 halves
constexpr int SSTAGE = SA + SB;           // 18432 halves
constexpr int STAGE_B = SSTAGE * 2;       // 36864 bytes
constexpr int SMEM_BYTES = STG * STAGE_B; // 73728
}

__global__ void __launch_bounds__(128, 2) k_gemm2(float* __restrict__ out)
{
    using namespace g2;
    extern __shared__ __half sm[];
    const int tid  = threadIdx.x;
    const int lane = tid & 31;
    const int warp = tid >> 5;
    const int m0 = blockIdx.x * BM;
    const int n0 = blockIdx.y * BN;
    const int wm = (warp & 1) * 64;
    const int wn = (warp >> 1) * 64;

    float acc[4][8][4] = {};   // [mi][nt][4]

    auto load_stage = [&](int s, int kt) {
        const int k0 = kt * BK;
        __half* sA = sm + s * SSTAGE;
        __half* sB = sA + SA;
#pragma unroll
        for (int i = 0; i < 8; i++) {
            int c = tid + i * 128;
            int r = c >> 3, kc = c & 7;
            cp16(sA + r * LDK + kc * 8,
                 g_hh + (size_t)(m0 + r) * INTER + k0 + kc * 8);
        }
#pragma unroll
        for (int i = 0; i < 8; i++) {
            int c = tid + i * 128;
            int r = c >> 3, kc = c & 7;
            cp16(sB + r * LDK + kc * 8,
                 g_w2h + (size_t)(n0 + r) * INTER + k0 + kc * 8);
        }
    };

    const uint32_t smb = smem_u32(sm);
    const int a_row = lane & 15;
    const int a_col = (lane >> 4) * 8;
    const int g = lane >> 3;
    const int b_row = (g & 1) * 8 + (lane & 7);
    const int b_col = (g >> 1) * 8;
    uint32_t a_off[4], b_off[4];
#pragma unroll
    for (int mi = 0; mi < 4; mi++)
        a_off[mi] = smb + ((wm + mi * 16 + a_row) * LDK + a_col) * 2;
#pragma unroll
    for (int nj = 0; nj < 4; nj++)
        b_off[nj] = smb + SA * 2 + ((wn + nj * 16 + b_row) * LDK + b_col) * 2;

    const int KT = INTER / BK;  // 224
    load_stage(0, 0);
    cp_commit();

    for (int kt = 0; kt < KT; ++kt) {
        cp_wait<0>();
        __syncthreads();
        if (kt + 1 < KT) load_stage((kt + 1) & 1, kt + 1);
        cp_commit();

        const uint32_t sbase = (kt & 1) * (uint32_t)STAGE_B;
#pragma unroll
        for (int kk16 = 0; kk16 < 4; kk16++) {
            const uint32_t ko = sbase + (uint32_t)kk16 * 32;
            uint32_t af[4][4];
#pragma unroll
            for (int mi = 0; mi < 4; mi++)
                ldsm_x4u(af[mi], a_off[mi] + ko);
            uint32_t bf[4][4];
#pragma unroll
            for (int nj = 0; nj < 4; nj++)
                ldsm_x4u(bf[nj], b_off[nj] + ko);
#pragma unroll
            for (int mi = 0; mi < 4; mi++)
#pragma unroll
                for (int nj = 0; nj < 4; nj++) {
                    mma_16816(acc[mi][2 * nj],     af[mi], bf[nj][0], bf[nj][2]);
                    mma_16816(acc[mi][2 * nj + 1], af[mi], bf[nj][1], bf[nj][3]);
                }
        }
    }

#pragma unroll
    for (int mi = 0; mi < 4; mi++) {
#pragma unroll
        for (int nt = 0; nt < 8; nt++) {
            const float* a = acc[mi][nt];
            int row = m0 + wm + mi * 16 + (lane >> 2);
            int col = n0 + wn + nt * 8 + 2 * (lane & 3);
            float2 lo = make_float2(a[0] * H_UNSCALE, a[1] * H_UNSCALE);
            float2 hi = make_float2(a[2] * H_UNSCALE, a[3] * H_UNSCALE);
            *reinterpret_cast<float2*>(out + (size_t)row * HID + col) = lo;
            *reinterpret_cast<float2*>(out + (size_t)(row + 8) * HID + col) = hi;
        }
    }
}

// ---------------------------------------------------------------------------
// Launch. k_gemm1 stays at launch index 4 (the slot ncu samples).
// ---------------------------------------------------------------------------
extern "C" void kernel_launch(void* const* d_in, const int* in_sizes, int n_in,
                              void* d_out, int out_size)
{
    (void)in_sizes; (void)n_in; (void)out_size;
    const float* x   = (const float*)d_in[0];
    const int*   w1q = (const int*)  d_in[1];
    const float* w1s = (const float*)d_in[2];
    const float* w1z = (const float*)d_in[3];
    const int*   w3q = (const int*)  d_in[4];
    const float* w3s = (const float*)d_in[5];
    const float* w3z = (const float*)d_in[6];
    const int*   w2q = (const int*)  d_in[7];
    const float* w2s = (const float*)d_in[8];
    const float* w2z = (const float*)d_in[9];
    float* out = (float*)d_out;

    void* p;
    cudaGetSymbolAddress(&p, g_w1h); __half* w1h = (__half*)p;
    cudaGetSymbolAddress(&p, g_w3h); __half* w3h = (__half*)p;
    cudaGetSymbolAddress(&p, g_w2h); __half* w2h = (__half*)p;

    cudaFuncSetAttribute(k_gemm1, cudaFuncAttributeMaxDynamicSharedMemorySize,
                         g1::SMEM_BYTES);
    cudaFuncSetAttribute(k_gemm2, cudaFuncAttributeMaxDynamicSharedMemorySize,
                         g2::SMEM_BYTES);

    int t8 = INTER * HID / 8;
    int blocks = (t8 + 255) / 256;
    int t4 = TOKS * HID / 4;

    // 1, 2, 3: inputs of GEMM1
    k_dequant<<<blocks, 256>>>(w1q, w1s, w1z, w1h, HID, HID / GSZ, t8);
    k_dequant<<<blocks, 256>>>(w3q, w3s, w3z, w3h, HID, HID / GSZ, t8);
    k_xconv<<<(t4 + 255) / 256, 256>>>(x, t4);
    // 4: GEMM1 (gate/up + SwiGLU)
    k_gemm1<<<dim3(TOKS / g1::BM, INTER / g1::BN), 128, g1::SMEM_BYTES>>>();
    // 5: dequant W2 (only needed by GEMM2)
    k_dequant<<<blocks, 256>>>(w2q, w2s, w2z, w2h, INTER, INTER / GSZ, t8);
    // 6: GEMM2 (down proj)
    k_gemm2<<<dim3(TOKS / g2::BM, HID / g2::BN), 128, g2::SMEM_BYTES>>>(out);
}